// round 14
// baseline (speedup 1.0000x reference)
#include <cuda_runtime.h>
#include <cstdint>

#define NB 64
#define NT 4096
#define NS 64
#define NQ 4
#define NTHREADS (NS * NQ)

__device__ __forceinline__ void fma2(unsigned long long &d, unsigned long long a, unsigned long long b) {
    asm("fma.rn.f32x2 %0, %1, %2, %0;" : "+l"(d) : "l"(a), "l"(b));
}
__device__ __forceinline__ unsigned long long add2(unsigned long long a, unsigned long long b) {
    unsigned long long d;
    asm("add.rn.f32x2 %0, %1, %2;" : "=l"(d) : "l"(a), "l"(b));
    return d;
}
__device__ __forceinline__ unsigned long long pk2(float lo, float hi) {
    unsigned long long d;
    asm("mov.b64 %0, {%1, %2};" : "=l"(d) : "f"(lo), "f"(hi));
    return d;
}

__global__ __launch_bounds__(NTHREADS, 1) void hmm_forward_kernel(
    const float* __restrict__ trans,   // (S,S)
    const float* __restrict__ emis,    // (B,T,S)
    float* __restrict__ alpha_out,     // (B,T,S)
    float* __restrict__ logz_out)      // (B,)
{
    const int b = blockIdx.x;
    const int tid = threadIdx.x;
    const int j = tid & (NS - 1);     // state 0..63
    const int q = tid >> 6;           // i-split group 0..3

    __shared__ __align__(16) float su[2][NS];        // u = exp(alpha - N), parity buffered
    __shared__ __align__(16) float spart[NS * NQ];   // partial dots, [j*4 + q]
    __shared__ float ring[4];                        // r_t = alpha_t[0]

    // eA[k] = (e^{A[i0][j]}, e^{A[i0+1][j]}), i0 = 16q + 2k  (this thread's 16-row slice)
    unsigned long long eA[8];
#pragma unroll
    for (int k = 0; k < 8; k++) {
        int i0 = 16 * q + 2 * k;
        float e0 = __expf(trans[i0 * NS + j]);
        float e1 = __expf(trans[(i0 + 1) * NS + j]);
        eA[k] = pk2(e0, e1);
    }

    const float* eb = emis + (size_t)b * NT * NS;
    float* ob = alpha_out + (size_t)b * NT * NS;

    // --- t = 0 ---
    float a0 = eb[j];                                  // alpha_0[j]
    if (q == 1) ob[j] = a0;
    if (tid == 0) { ring[0] = a0; ring[2] = a0; ring[3] = a0; }  // r_0, r_{-1}, r_{-2}

    // Emission prefetch (role-specific):
    //   q1 consumes e_t at step t:    ebuf[(t-1)&3], init e_1..e_4, refill e_{t+4}
    //   q0 consumes e_{t+1} at step t: ebuf[(t-1)&3], init e_2..e_5, refill e_{t+5}
    float ebuf[4] = {0, 0, 0, 0};
    if (q == 1) {
#pragma unroll
        for (int p = 0; p < 4; p++) ebuf[p] = eb[(size_t)(1 + p) * NS + j];
    } else if (q == 0) {
#pragma unroll
        for (int p = 0; p < 4; p++) ebuf[p] = eb[(size_t)(2 + p) * NS + j];
    }

    __syncthreads();
    float f = 0.0f;
    if (q == 0) {
        float N0 = ring[0];
        su[0][j] = __expf(a0 - N0);        // u(0)
        f = __expf(eb[NS + j]);            // f_1 = exp(e_1 - 0)
    }
    __syncthreads();

    // --- Main recurrence: exact stale-normalizer scheme (see R10) ---
    // u_j(t) = exp(alpha_t[j] - r_{t-2});  alpha_t = log s + r_{t-3} + e_t (exact).
#pragma unroll 2
    for (int t = 1; t < NT; t++) {
        const int buf = t & 1;

        // Phase A (all 256 threads): 16-term partial dot over i in [16q, 16q+16)
        const ulonglong2* sp = reinterpret_cast<const ulonglong2*>(&su[buf ^ 1][16 * q]);
        unsigned long long acc0 = 0ull, acc1 = 0ull;
#pragma unroll
        for (int k = 0; k < 4; k++) {
            ulonglong2 qa = sp[k];
            fma2(acc0, qa.x, eA[2 * k]);
            fma2(acc1, qa.y, eA[2 * k + 1]);
        }
        unsigned long long s2 = add2(acc0, acc1);
        float lo, hi;
        asm("mov.b64 {%0, %1}, %2;" : "=f"(lo), "=f"(hi) : "l"(s2));
        spart[j * 4 + q] = lo + hi;
        __syncthreads();   // BAR1

        // Phase B (role-specialized)
        if (q == 0) {
            float4 pp = *reinterpret_cast<const float4*>(&spart[j * 4]);
            float s = (pp.x + pp.y) + (pp.z + pp.w);
            su[buf][j] = s * f;                           // u(t)
            // prepare f_{t+1} = exp(e_{t+1} - (r_{t-1} - r_{t-2}))  [latency hides under BAR2]
            float dM = ring[(t - 1) & 3] - ring[(t - 2) & 3];
            float e_next = ebuf[(t - 1) & 3];             // e_{t+1}
            ebuf[(t - 1) & 3] = (t + 5 < NT) ? eb[(size_t)(t + 5) * NS + j] : 0.0f;
            f = __expf(e_next - dM);
        } else if (q == 1) {
            float4 pp = *reinterpret_cast<const float4*>(&spart[j * 4]);
            float s = (pp.x + pp.y) + (pp.z + pp.w);
            float Nprev = ring[(t + 1) & 3];              // r_{t-3}
            float e_cur = ebuf[(t - 1) & 3];              // e_t
            float aout = __logf(s) + Nprev + e_cur;       // alpha_t[j], exact
            ob[(size_t)t * NS + j] = aout;
            if (j == 0) ring[t & 3] = aout;               // publish r_t
            ebuf[(t - 1) & 3] = (t + 4 < NT) ? eb[(size_t)(t + 4) * NS + j] : 0.0f;
            a0 = aout;                                    // carry final alpha
        }
        __syncthreads();   // BAR2
    }

    // --- log_Z = logsumexp over final alpha ---
    if (q == 1) su[0][j] = a0;
    __syncthreads();
    if (tid == 0) {
        float mx = su[0][0];
#pragma unroll
        for (int i = 1; i < NS; i++) mx = fmaxf(mx, su[0][i]);
        float tot = 0.0f;
#pragma unroll
        for (int i = 0; i < NS; i++) tot += __expf(su[0][i] - mx);
        logz_out[b] = mx + __logf(tot);
    }
}

extern "C" void kernel_launch(void* const* d_in, const int* in_sizes, int n_in,
                              void* d_out, int out_size) {
    const float* trans = (const float*)d_in[0];  // (S,S) fp32
    const float* emis  = (const float*)d_in[1];  // (B,T,S) fp32
    // d_in[2] = seq_lens (unused by reference)
    float* alpha = (float*)d_out;                       // (B,T,S)
    float* logz  = alpha + (size_t)NB * NT * NS;        // (B,)
    hmm_forward_kernel<<<NB, NTHREADS>>>(trans, emis, alpha, logz);
}